// round 16
// baseline (speedup 1.0000x reference)
#include <cuda_runtime.h>
#include <cuda_bf16.h>
#include <cstddef>
#include <cstdint>

// Problem constants (CTCLoss_56298431315981): T=1024, B=32, C=1024, L=128
constexpr int kT = 1024;
constexpr int kB = 32;
constexpr int kC = 1024;
constexpr int kL = 128;
constexpr int kS = 2 * kL + 1;   // 257 extended states
constexpr int kRow = 256;        // floats per (b,t) row: 2 comps x 32 lanes x 4
constexpr int kTP = kT + 16;

// Scratch (static __device__ — no allocations allowed)
// Row layout (float4 view): comp0[lane] = {p(5l),p(5l+1),p(5l+2),p(5l+3)},
// comp1[lane] = {p(5l+4), blank, log2(rowmax), 0}; row-max normalized.
__device__ __align__(16) float g_E[(size_t)kB * kTP * kRow];
__device__ int   g_flag[kB * kTP];   // row-ready flags (zeroed each call)
__device__ float g_nll[kB];

// ---------------------------------------------------------------------------
__device__ __forceinline__ void twoFactor(int d, float& f1, float& f2)
{
    d = max(min(d, 252), -300);
    if (d < -252) { f1 = 0.f; f2 = 0.f; return; }
    const int dh = d / 2;
    f1 = __int_as_float((dh + 127) << 23);
    f2 = __int_as_float((d - dh + 127) << 23);
}

__device__ __forceinline__ float4 ldcg4(const float* p)
{
    float4 v;
    asm volatile("ld.global.cg.v4.f32 {%0,%1,%2,%3}, [%4];"
                 : "=f"(v.x), "=f"(v.y), "=f"(v.z), "=f"(v.w) : "l"(p));
    return v;
}
__device__ __forceinline__ int ldcg_s32(const int* p)
{
    int v;
    asm volatile("ld.global.cg.s32 %0, [%1];" : "=r"(v) : "l"(p));
    return v;
}
__device__ __forceinline__ float ldcg_f32(const float* p)
{
    float v;
    asm volatile("ld.global.cg.f32 %0, [%1];" : "=f"(v) : "l"(p));
    return v;
}
__device__ __forceinline__ void stcg_s32(int* p, int v)
{
    asm volatile("st.global.cg.s32 [%0], %1;" :: "l"(p), "r"(v) : "memory");
}

// ---------------------------------------------------------------------------
// Kernel 0: zero the flag array (graph replays reuse it).
// ---------------------------------------------------------------------------
__global__ void ctc_zero_kernel()
{
    const int idx = blockIdx.x * 256 + threadIdx.x;
    if (idx < kB * kTP) g_flag[idx] = 0;
}

// ---------------------------------------------------------------------------
// Fused kernel. Blocks >= 32: emission producers, ENDS-FIRST t order, setting
// a per-row flag (st.global.cg after __threadfence). Blocks 0..31: DP for
// batch b = bid: warp 0 = forward alpha, warp 1 = backward beta, warps 2..7
// exit at the top. NO barriers in the DP path: warp1 -> warp0 result handoff
// uses store / __threadfence_block / volatile smem flag.
// ALL vector-cast shared arrays are __align__(16): a bare __shared__ float[]
// is only 4B-aligned, and the fused kernel's smem layout (producer + DP
// arrays) shifted them off 16B — the root cause of R14/R15's traps.
// ---------------------------------------------------------------------------
__global__ void __launch_bounds__(256) ctc_fused_kernel(
    const float* __restrict__ data, const int* __restrict__ labels,
    const int* __restrict__ llen, const int* __restrict__ dlen)
{
    const unsigned FULL = 0xffffffffu;
    const int NEGI = -(1 << 28);
    const int tid  = threadIdx.x;
    const int lane = tid & 31;
    const int w    = tid >> 5;

    if (blockIdx.x >= 32) {
        // ===================== PRODUCER =====================================
        __shared__ __align__(16) float sh[8][kC];
        __shared__ __align__(16) int   shlab[8][kL];
        const int g    = ((blockIdx.x - 32) << 3) + w;   // 0 .. T*B-1
        const int b    = g & 31;
        const int tlin = g >> 5;
        const int jj   = tlin >> 1;
        const int t    = (tlin & 1) ? (1023 - jj) : jj;  // ENDS FIRST

        reinterpret_cast<int4*>(shlab[w])[lane] =
            reinterpret_cast<const int4*>(labels + b * kL)[lane];

        const float4* src =
            reinterpret_cast<const float4*>(data + (size_t)(t * kB + b) * kC);

        float m = -3.4e38f;
        float4 v[8];
#pragma unroll
        for (int i = 0; i < 8; i++) {
            v[i] = src[(i << 5) + lane];
            reinterpret_cast<float4*>(sh[w])[(i << 5) + lane] = v[i];
            m = fmaxf(m, fmaxf(fmaxf(v[i].x, v[i].y), fmaxf(v[i].z, v[i].w)));
        }
#pragma unroll
        for (int o = 16; o; o >>= 1) m = fmaxf(m, __shfl_xor_sync(FULL, m, o));

        float ssum = 0.f;
#pragma unroll
        for (int i = 0; i < 8; i++) {
            ssum += __expf(v[i].x - m) + __expf(v[i].y - m) +
                    __expf(v[i].z - m) + __expf(v[i].w - m);
        }
#pragma unroll
        for (int o = 16; o; o >>= 1) ssum += __shfl_xor_sync(FULL, ssum, o);

        const float lse = m + __logf(ssum);
        __syncwarp();

        const float blank = __expf(sh[w][0] - lse);
        float p[5];
#pragma unroll
        for (int j = 0; j < 5; j++) {
            const int idx = 5 * lane + j;
            p[j] = (idx < kL) ? __expf(sh[w][shlab[w][idx]] - lse) : 0.f;
        }
        float pmax = fmaxf(fmaxf(fmaxf(p[0], p[1]), fmaxf(p[2], p[3])),
                           fmaxf(p[4], blank));
#pragma unroll
        for (int o = 16; o; o >>= 1) pmax = fmaxf(pmax, __shfl_xor_sync(FULL, pmax, o));

        const float r   = __frcp_rn(pmax);
        const float lg2 = -__log2f(r);

        float4* dst = reinterpret_cast<float4*>(g_E + ((size_t)b * kTP + t) * kRow);
        dst[lane]      = make_float4(p[0] * r, p[1] * r, p[2] * r, p[3] * r);
        dst[32 + lane] = make_float4(p[4] * r, blank * r, lg2, 0.f);

        __syncwarp();                       // all lanes' row stores done
        if (lane == 0) {
            __threadfence();                // rows visible before flag
            stcg_s32(&g_flag[b * kTP + t], 1);
        }
        return;
    }

    // ========================= DP BLOCK =====================================
    __shared__ __align__(16) float AFs[320];
    __shared__ __align__(16) float BBs[320];
    __shared__ __align__(16) int   XFs[32];
    __shared__ __align__(16) int   XBs[32];
    __shared__ __align__(16) float LGs[2];
    __shared__ int doneB;

    if (w >= 2) return;                    // exit BEFORE any sync construct

    const int b = blockIdx.x;
    if (w == 0 && lane == 0) *(volatile int*)&doneB = 0;

    const int len = llen[b];
    const int Tb  = dlen[b];               // 512..1024
    const int mid = (Tb - 1) >> 1;
    const int rem = Tb - 1 - mid;
    const float* __restrict__ Eb  = g_E + (size_t)b * kTP * kRow;
    const int*   __restrict__ lab = labels + b * kL;
    const int*   __restrict__ flg = g_flag + b * kTP;

    if (w == 0) {
        // ===================== FORWARD (alpha), t = 0..mid ==================
        float allow[5];
#pragma unroll
        for (int k = 0; k < 5; k++) {
            const int li = 5 * lane + k;
            bool al = false;
            if (li >= 1 && li < kL) al = (lab[li] != lab[li - 1]);
            allow[k] = al ? 1.0f : 0.0f;
        }

        // Wait rows 0..6 (init + 6-row ring).
        {
            int ok;
            do {
                const int f = (lane < 7) ? ldcg_s32(flg + lane) : 1;
                ok = __all_sync(FULL, f != 0);
            } while (!ok);
        }

        float a[10];
#pragma unroll
        for (int j = 0; j < 10; j++) a[j] = 0.f;
        float lgsum = ldcg_f32(Eb + 130);             // row0 log2(pmax)
        if (lane == 0) {
            const float4 c0 = ldcg4(Eb);
            const float4 c1 = ldcg4(Eb + 128);
            a[0] = c1.y;                              // blank
            a[1] = c0.x;                              // label 0
        }
        int   X   = 0;
        float sD1 = (lane == 0) ? 0.f : 1.f;
        float sD2 = (lane == 0) ? 0.f : 1.f;

        float4 P[6][2];
#pragma unroll
        for (int q = 0; q < 6; q++) {
            const float* r = Eb + (size_t)(1 + q) * kRow;
            P[q][0] = ldcg4(r + 4 * lane);
            P[q][1] = ldcg4(r + 128 + 4 * lane);
        }

        auto dostep = [&](const float4* Pq) {
            float h1 = __shfl_up_sync(FULL, a[9], 1);
            h1 = (h1 * sD1) * sD2;
            const float bl = Pq[1].y;
            lgsum += Pq[1].z;
            float na[10];
            na[0] = (a[0] + h1) * bl;
            na[1] = fmaf(allow[0], h1,   a[1] + a[0]) * Pq[0].x;
            na[2] = (a[2] + a[1]) * bl;
            na[3] = fmaf(allow[1], a[1], a[3] + a[2]) * Pq[0].y;
            na[4] = (a[4] + a[3]) * bl;
            na[5] = fmaf(allow[2], a[3], a[5] + a[4]) * Pq[0].z;
            na[6] = (a[6] + a[5]) * bl;
            na[7] = fmaf(allow[3], a[5], a[7] + a[6]) * Pq[0].w;
            na[8] = (a[8] + a[7]) * bl;
            na[9] = fmaf(allow[4], a[7], a[9] + a[8]) * Pq[1].x;
#pragma unroll
            for (int j = 0; j < 10; j++) a[j] = na[j];
        };
        auto pref = [&](float4* Pq, int trow) {
            const float* r = Eb + (size_t)trow * kRow;
            Pq[0] = ldcg4(r + 4 * lane);
            Pq[1] = ldcg4(r + 128 + 4 * lane);
        };
        auto rescale = [&]() {
            float mm = a[0];
#pragma unroll
            for (int j = 1; j < 10; j++) mm = fmaxf(mm, a[j]);
            const bool nz = (mm > 0.f);
            const int  e    = nz ? (((__float_as_int(mm) >> 23) & 0xff) - 127) : 0;
            const int  cand = nz ? (X + e) : NEGI;
            const int  c1 = __shfl_up_sync(FULL, cand, 1);
            const int  c2 = __shfl_up_sync(FULL, cand, 2);
            int Xn;
            if (lane == 0) {
                Xn = nz ? cand : X;
            } else {
                const int low  = max(c1 - 24, c2 - 48);
                const int ownc = nz ? cand : NEGI;
                Xn = max(ownc, low);
                if (Xn <= NEGI) Xn = X;
            }
            float f1, f2;
            twoFactor(X - Xn, f1, f2);
#pragma unroll
            for (int j = 0; j < 10; j++) a[j] = (a[j] * f1) * f2;
            X = Xn;
            const int Xp = __shfl_up_sync(FULL, X, 1);
            twoFactor(Xp - X, sD1, sD2);
            if (lane == 0) { sD1 = 0.f; sD2 = 0.f; }
        };

        // Pipelined flag check: pend covers rows t+6..t+11 of this group.
        int pend = (lane < 6) ? ldcg_s32(flg + 7 + lane) : 1;
        int t = 1;
        for (; t + 5 <= mid; t += 6) {
            while (!__all_sync(FULL, pend != 0))
                pend = (lane < 6) ? ldcg_s32(flg + t + 6 + lane) : 1;
            const int npend = (lane < 6) ? ldcg_s32(flg + t + 12 + lane) : 1;
            dostep(P[0]); pref(P[0], t + 6);
            dostep(P[1]); pref(P[1], t + 7);
            dostep(P[2]); pref(P[2], t + 8);
            dostep(P[3]); pref(P[3], t + 9);
            dostep(P[4]); pref(P[4], t + 10);
            dostep(P[5]); pref(P[5], t + 11);
            rescale();
            pend = npend;
        }
        if (t <= mid) { dostep(P[0]); ++t; }
        if (t <= mid) { dostep(P[1]); ++t; }
        if (t <= mid) { dostep(P[2]); ++t; }
        if (t <= mid) { dostep(P[3]); ++t; }
        if (t <= mid) { dostep(P[4]); ++t; }

#pragma unroll
        for (int j = 0; j < 10; j++) AFs[10 * lane + j] = a[j];
        XFs[lane] = X;
        if (lane == 0) LGs[0] = lgsum;

        // Wait for backward warp's results (volatile smem handshake).
        if (lane == 0) {
            while (*(volatile int*)&doneB == 0) { }
        }
        __syncwarp();
        __threadfence_block();

        // ===== Combine: log2 L = LSE_s [lg aF + XF + lg bB + XB] + lgsums ===
        float ys[9];
        float ymax = -1e30f;
#pragma unroll
        for (int k = 0; k < 9; k++) {
            const int s = lane + 32 * k;
            float y = -1e30f;
            if (s < kS) {
                const float af = AFs[s], bb = BBs[s];
                if (af > 0.f && bb > 0.f)
                    y = log2f(af) + log2f(bb) + (float)(XFs[s / 10] + XBs[s / 10]);
            }
            ys[k] = y;
            ymax = fmaxf(ymax, y);
        }
#pragma unroll
        for (int o = 16; o; o >>= 1) ymax = fmaxf(ymax, __shfl_xor_sync(FULL, ymax, o));
        float ssum = 0.f;
#pragma unroll
        for (int k = 0; k < 9; k++) ssum += exp2f(ys[k] - ymax);
#pragma unroll
        for (int o = 16; o; o >>= 1) ssum += __shfl_xor_sync(FULL, ssum, o);
        if (lane == 0) {
            const float rr = ymax + log2f(ssum) + LGs[0] + LGs[1];
            g_nll[b] = -rr * 0.69314718055994530942f;   // log2 -> ln
        }
    } else {
        // ===================== BACKWARD (beta), t = Tb-1..mid ===============
        float allowB[5];
#pragma unroll
        for (int k = 0; k < 5; k++) {
            const int li = 5 * lane + k + 1;
            bool al = false;
            if (li < kL) al = (lab[li] != lab[li - 1]);
            allowB[k] = al ? 1.0f : 0.0f;
        }

        const int sBl = 2 * len, sLl = sBl - 1;
        float bv[10];
#pragma unroll
        for (int j = 0; j < 10; j++) {
            const int s = 10 * lane + j;
            bv[j] = (s == sBl || s == sLl) ? 1.f : 0.f;
        }
        float lgsum = 0.f;
        int   X   = 0;
        float sB1 = (lane == 31) ? 0.f : 1.f;
        float sB2 = (lane == 31) ? 0.f : 1.f;

        // Wait distances 0..5 (rows Tb-1 .. Tb-6).
        {
            int ok;
            do {
                const int f = (lane < 6) ? ldcg_s32(flg + Tb - 1 - lane) : 1;
                ok = __all_sync(FULL, f != 0);
            } while (!ok);
        }

        float4 P[6][2];
#pragma unroll
        for (int q = 0; q < 6; q++) {
            const float* r = Eb + (size_t)(Tb - 1 - q) * kRow;
            P[q][0] = ldcg4(r + 4 * lane);
            P[q][1] = ldcg4(r + 128 + 4 * lane);
        }

        auto dostepB = [&](const float4* Pq) {
            const float bl = Pq[1].y;
            lgsum += Pq[1].z;
            float c[10];
            c[0] = bv[0] * bl;  c[1] = bv[1] * Pq[0].x;
            c[2] = bv[2] * bl;  c[3] = bv[3] * Pq[0].y;
            c[4] = bv[4] * bl;  c[5] = bv[5] * Pq[0].z;
            c[6] = bv[6] * bl;  c[7] = bv[7] * Pq[0].w;
            c[8] = bv[8] * bl;  c[9] = bv[9] * Pq[1].x;
            float h0 = __shfl_down_sync(FULL, c[0], 1);
            float h1 = __shfl_down_sync(FULL, c[1], 1);
            h0 = (h0 * sB1) * sB2;
            h1 = (h1 * sB1) * sB2;
            float nb[10];
            nb[0] = c[0] + c[1];
            nb[1] = fmaf(allowB[0], c[3], c[1] + c[2]);
            nb[2] = c[2] + c[3];
            nb[3] = fmaf(allowB[1], c[5], c[3] + c[4]);
            nb[4] = c[4] + c[5];
            nb[5] = fmaf(allowB[2], c[7], c[5] + c[6]);
            nb[6] = c[6] + c[7];
            nb[7] = fmaf(allowB[3], c[9], c[7] + c[8]);
            nb[8] = c[8] + c[9];
            nb[9] = fmaf(allowB[4], h1,   c[9] + h0);
#pragma unroll
            for (int j = 0; j < 10; j++) bv[j] = nb[j];
        };
        auto prefB = [&](float4* Pq, int dd) {
            const float* r = Eb + (size_t)(Tb - 1 - dd) * kRow;
            Pq[0] = ldcg4(r + 4 * lane);
            Pq[1] = ldcg4(r + 128 + 4 * lane);
        };
        auto rescaleB = [&]() {
            float mm = bv[0];
#pragma unroll
            for (int j = 1; j < 10; j++) mm = fmaxf(mm, bv[j]);
            const bool nz = (mm > 0.f);
            const int  e    = nz ? (((__float_as_int(mm) >> 23) & 0xff) - 127) : 0;
            const int  cand = nz ? (X + e) : NEGI;
            const int  c1 = __shfl_down_sync(FULL, cand, 1);
            const int  c2 = __shfl_down_sync(FULL, cand, 2);
            int Xn;
            if (lane == 31) {
                Xn = nz ? cand : X;
            } else {
                const int low  = max(c1 - 24, c2 - 48);
                const int ownc = nz ? cand : NEGI;
                Xn = max(ownc, low);
                if (Xn <= NEGI) Xn = X;
            }
            float f1, f2;
            twoFactor(X - Xn, f1, f2);
#pragma unroll
            for (int j = 0; j < 10; j++) bv[j] = (bv[j] * f1) * f2;
            X = Xn;
            const int Xp = __shfl_down_sync(FULL, X, 1);
            twoFactor(Xp - X, sB1, sB2);
            if (lane == 31) { sB1 = 0.f; sB2 = 0.f; }
        };

        // Pipelined flag check: pend covers distances d+6..d+11.
        int pend = (lane < 6) ? ldcg_s32(flg + Tb - 7 - lane) : 1;
        int d = 0;
        for (; d + 6 <= rem; d += 6) {
            while (!__all_sync(FULL, pend != 0))
                pend = (lane < 6) ? ldcg_s32(flg + Tb - 7 - d - lane) : 1;
            const int npend = (lane < 6) ? ldcg_s32(flg + Tb - 13 - d - lane) : 1;
            dostepB(P[0]); prefB(P[0], d + 6);
            dostepB(P[1]); prefB(P[1], d + 7);
            dostepB(P[2]); prefB(P[2], d + 8);
            dostepB(P[3]); prefB(P[3], d + 9);
            dostepB(P[4]); prefB(P[4], d + 10);
            dostepB(P[5]); prefB(P[5], d + 11);
            rescaleB();
            pend = npend;
        }
        if (d < rem) { dostepB(P[0]); ++d; }
        if (d < rem) { dostepB(P[1]); ++d; }
        if (d < rem) { dostepB(P[2]); ++d; }
        if (d < rem) { dostepB(P[3]); ++d; }
        if (d < rem) { dostepB(P[4]); ++d; }

#pragma unroll
        for (int j = 0; j < 10; j++) BBs[10 * lane + j] = bv[j];
        XBs[lane] = X;
        if (lane == 0) LGs[1] = lgsum;

        // Publish: results visible before the done flag.
        __syncwarp();
        __threadfence_block();
        if (lane == 0) *(volatile int*)&doneB = 1;
    }
}

// ---------------------------------------------------------------------------
// Kernel 3: mean over batch -> d_out[0]. Deterministic (no atomics).
// ---------------------------------------------------------------------------
__global__ void ctc_finish_kernel(float* __restrict__ out)
{
    float v = g_nll[threadIdx.x];
#pragma unroll
    for (int o = 16; o; o >>= 1) v += __shfl_xor_sync(0xffffffffu, v, o);
    if (threadIdx.x == 0) out[0] = v * (1.0f / kB);
}

extern "C" void kernel_launch(void* const* d_in, const int* in_sizes, int n_in,
                              void* d_out, int out_size)
{
    const int*   labels       = (const int*)d_in[0];
    const float* data         = (const float*)d_in[1];
    const int*   label_length = (const int*)d_in[2];
    const int*   data_length  = (const int*)d_in[3];
    float*       out          = (float*)d_out;

    ctc_zero_kernel<<<(kB * kTP + 255) / 256, 256>>>();
    ctc_fused_kernel<<<32 + (kT * kB) / 8, 256>>>(data, labels,
                                                  label_length, data_length);
    ctc_finish_kernel<<<1, 32>>>(out);
}

// round 17
// speedup vs baseline: 1.0744x; 1.0744x over previous
#include <cuda_runtime.h>
#include <cuda_bf16.h>
#include <cstddef>
#include <cstdint>

// Problem constants (CTCLoss_56298431315981): T=1024, B=32, C=1024, L=128
constexpr int kT = 1024;
constexpr int kB = 32;
constexpr int kC = 1024;
constexpr int kL = 128;
constexpr int kS = 2 * kL + 1;   // 257 extended states
constexpr int kRow = 256;        // floats per (b,t) row: 2 comps x 32 lanes x 4
constexpr int kTP = kT + 16;

constexpr int kGrid  = 148;      // ONE WAVE: one block per SM (bijective LUT)
constexpr int kNProdBlocks = kGrid - 32;        // 116 producer blocks
constexpr int kNProdWarps  = kNProdBlocks * 8;  // 928 producer warps

// Scratch (static __device__ — no allocations allowed)
// Row layout (float4 view): comp0[lane] = {p(5l),p(5l+1),p(5l+2),p(5l+3)},
// comp1[lane] = {p(5l+4), blank, log2(rowmax), 0}; row-max normalized.
__device__ __align__(16) float g_E[(size_t)kB * kTP * kRow];
__device__ int   g_flag[kB * kTP];   // row-ready flags (zeroed each call)
__device__ float g_nll[kB];

// ---------------------------------------------------------------------------
__device__ __forceinline__ void twoFactor(int d, float& f1, float& f2)
{
    d = max(min(d, 252), -300);
    if (d < -252) { f1 = 0.f; f2 = 0.f; return; }
    const int dh = d / 2;
    f1 = __int_as_float((dh + 127) << 23);
    f2 = __int_as_float((d - dh + 127) << 23);
}

__device__ __forceinline__ float4 ldcg4(const float* p)
{
    float4 v;
    asm volatile("ld.global.cg.v4.f32 {%0,%1,%2,%3}, [%4];"
                 : "=f"(v.x), "=f"(v.y), "=f"(v.z), "=f"(v.w) : "l"(p));
    return v;
}
__device__ __forceinline__ int ldcg_s32(const int* p)
{
    int v;
    asm volatile("ld.global.cg.s32 %0, [%1];" : "=r"(v) : "l"(p));
    return v;
}
__device__ __forceinline__ float ldcg_f32(const float* p)
{
    float v;
    asm volatile("ld.global.cg.f32 %0, [%1];" : "=f"(v) : "l"(p));
    return v;
}
__device__ __forceinline__ void stcg_s32(int* p, int v)
{
    asm volatile("st.global.cg.s32 [%0], %1;" :: "l"(p), "r"(v) : "memory");
}

// ---------------------------------------------------------------------------
// Kernel 0: zero the flag array (graph replays reuse it).
// ---------------------------------------------------------------------------
__global__ void ctc_zero_kernel()
{
    const int idx = blockIdx.x * 256 + threadIdx.x;
    if (idx < kB * kTP) g_flag[idx] = 0;
}

// ---------------------------------------------------------------------------
// Fused kernel, ONE WAVE of 148 blocks (one per SM).
// Blocks 32..147: PERSISTENT producers — 928 warps loop over all 32768 rows
//   in ENDS-FIRST global order, flag per row (st.cg after __threadfence).
// Blocks 0..31: DP for batch b = bid on an otherwise-idle SM: warp 0 =
//   forward alpha, warp 1 = backward beta, warps 2..7 exit at the top.
//   No barriers: warp1 -> warp0 handoff via volatile smem + fences.
// ---------------------------------------------------------------------------
__global__ void __launch_bounds__(256) ctc_fused_kernel(
    const float* __restrict__ data, const int* __restrict__ labels,
    const int* __restrict__ llen, const int* __restrict__ dlen)
{
    const unsigned FULL = 0xffffffffu;
    const int NEGI = -(1 << 28);
    const int tid  = threadIdx.x;
    const int lane = tid & 31;
    const int w    = tid >> 5;

    if (blockIdx.x >= 32) {
        // ================= PERSISTENT PRODUCER ==============================
        __shared__ __align__(16) float sh[8][kC];
        __shared__ __align__(16) int   shlab[8][kL];

        for (int g = ((int)blockIdx.x - 32) * 8 + w; g < kT * kB;
             g += kNProdWarps) {
            const int b    = g & 31;
            const int tlin = g >> 5;
            const int jj   = tlin >> 1;
            const int t    = (tlin & 1) ? (1023 - jj) : jj;  // ENDS FIRST

            reinterpret_cast<int4*>(shlab[w])[lane] =
                reinterpret_cast<const int4*>(labels + b * kL)[lane];

            const float4* src =
                reinterpret_cast<const float4*>(data + (size_t)(t * kB + b) * kC);

            float m = -3.4e38f;
            float4 v[8];
#pragma unroll
            for (int i = 0; i < 8; i++) {
                v[i] = src[(i << 5) + lane];
                reinterpret_cast<float4*>(sh[w])[(i << 5) + lane] = v[i];
                m = fmaxf(m, fmaxf(fmaxf(v[i].x, v[i].y), fmaxf(v[i].z, v[i].w)));
            }
#pragma unroll
            for (int o = 16; o; o >>= 1) m = fmaxf(m, __shfl_xor_sync(FULL, m, o));

            float ssum = 0.f;
#pragma unroll
            for (int i = 0; i < 8; i++) {
                ssum += __expf(v[i].x - m) + __expf(v[i].y - m) +
                        __expf(v[i].z - m) + __expf(v[i].w - m);
            }
#pragma unroll
            for (int o = 16; o; o >>= 1) ssum += __shfl_xor_sync(FULL, ssum, o);

            const float lse = m + __logf(ssum);
            __syncwarp();                   // sh/shlab stores visible warp-wide

            const float blank = __expf(sh[w][0] - lse);
            float p[5];
#pragma unroll
            for (int j = 0; j < 5; j++) {
                const int idx = 5 * lane + j;
                p[j] = (idx < kL) ? __expf(sh[w][shlab[w][idx]] - lse) : 0.f;
            }
            float pmax = fmaxf(fmaxf(fmaxf(p[0], p[1]), fmaxf(p[2], p[3])),
                               fmaxf(p[4], blank));
#pragma unroll
            for (int o = 16; o; o >>= 1)
                pmax = fmaxf(pmax, __shfl_xor_sync(FULL, pmax, o));

            const float r   = __frcp_rn(pmax);
            const float lg2 = -__log2f(r);

            float4* dst = reinterpret_cast<float4*>(
                g_E + ((size_t)b * kTP + t) * kRow);
            dst[lane]      = make_float4(p[0] * r, p[1] * r, p[2] * r, p[3] * r);
            dst[32 + lane] = make_float4(p[4] * r, blank * r, lg2, 0.f);

            __syncwarp();                   // all lanes' row stores done
            if (lane == 0) {
                __threadfence();            // rows visible before flag
                stcg_s32(&g_flag[b * kTP + t], 1);
            }
            __syncwarp();                   // protect sh reuse next iteration
        }
        return;
    }

    // ========================= DP BLOCK =====================================
    __shared__ __align__(16) float AFs[320];
    __shared__ __align__(16) float BBs[320];
    __shared__ __align__(16) int   XFs[32];
    __shared__ __align__(16) int   XBs[32];
    __shared__ __align__(16) float LGs[2];
    __shared__ int doneB;

    if (w >= 2) return;                    // exit BEFORE any sync construct

    const int b = blockIdx.x;
    if (w == 0 && lane == 0) *(volatile int*)&doneB = 0;

    const int len = llen[b];
    const int Tb  = dlen[b];               // 512..1024
    const int mid = (Tb - 1) >> 1;
    const int rem = Tb - 1 - mid;
    const float* __restrict__ Eb  = g_E + (size_t)b * kTP * kRow;
    const int*   __restrict__ lab = labels + b * kL;
    const int*   __restrict__ flg = g_flag + b * kTP;

    if (w == 0) {
        // ===================== FORWARD (alpha), t = 0..mid ==================
        float allow[5];
#pragma unroll
        for (int k = 0; k < 5; k++) {
            const int li = 5 * lane + k;
            bool al = false;
            if (li >= 1 && li < kL) al = (lab[li] != lab[li - 1]);
            allow[k] = al ? 1.0f : 0.0f;
        }

        // Wait rows 0..6 (init + 6-row ring).
        {
            int ok;
            do {
                const int f = (lane < 7) ? ldcg_s32(flg + lane) : 1;
                ok = __all_sync(FULL, f != 0);
            } while (!ok);
        }

        float a[10];
#pragma unroll
        for (int j = 0; j < 10; j++) a[j] = 0.f;
        float lgsum = ldcg_f32(Eb + 130);             // row0 log2(pmax)
        if (lane == 0) {
            const float4 c0 = ldcg4(Eb);
            const float4 c1 = ldcg4(Eb + 128);
            a[0] = c1.y;                              // blank
            a[1] = c0.x;                              // label 0
        }
        int   X   = 0;
        float sD1 = (lane == 0) ? 0.f : 1.f;
        float sD2 = (lane == 0) ? 0.f : 1.f;

        float4 P[6][2];
#pragma unroll
        for (int q = 0; q < 6; q++) {
            const float* r = Eb + (size_t)(1 + q) * kRow;
            P[q][0] = ldcg4(r + 4 * lane);
            P[q][1] = ldcg4(r + 128 + 4 * lane);
        }

        auto dostep = [&](const float4* Pq) {
            float h1 = __shfl_up_sync(FULL, a[9], 1);
            h1 = (h1 * sD1) * sD2;
            const float bl = Pq[1].y;
            lgsum += Pq[1].z;
            float na[10];
            na[0] = (a[0] + h1) * bl;
            na[1] = fmaf(allow[0], h1,   a[1] + a[0]) * Pq[0].x;
            na[2] = (a[2] + a[1]) * bl;
            na[3] = fmaf(allow[1], a[1], a[3] + a[2]) * Pq[0].y;
            na[4] = (a[4] + a[3]) * bl;
            na[5] = fmaf(allow[2], a[3], a[5] + a[4]) * Pq[0].z;
            na[6] = (a[6] + a[5]) * bl;
            na[7] = fmaf(allow[3], a[5], a[7] + a[6]) * Pq[0].w;
            na[8] = (a[8] + a[7]) * bl;
            na[9] = fmaf(allow[4], a[7], a[9] + a[8]) * Pq[1].x;
#pragma unroll
            for (int j = 0; j < 10; j++) a[j] = na[j];
        };
        auto pref = [&](float4* Pq, int trow) {
            const float* r = Eb + (size_t)trow * kRow;
            Pq[0] = ldcg4(r + 4 * lane);
            Pq[1] = ldcg4(r + 128 + 4 * lane);
        };
        auto rescale = [&]() {
            float mm = a[0];
#pragma unroll
            for (int j = 1; j < 10; j++) mm = fmaxf(mm, a[j]);
            const bool nz = (mm > 0.f);
            const int  e    = nz ? (((__float_as_int(mm) >> 23) & 0xff) - 127) : 0;
            const int  cand = nz ? (X + e) : NEGI;
            const int  c1 = __shfl_up_sync(FULL, cand, 1);
            const int  c2 = __shfl_up_sync(FULL, cand, 2);
            int Xn;
            if (lane == 0) {
                Xn = nz ? cand : X;
            } else {
                const int low  = max(c1 - 24, c2 - 48);
                const int ownc = nz ? cand : NEGI;
                Xn = max(ownc, low);
                if (Xn <= NEGI) Xn = X;
            }
            float f1, f2;
            twoFactor(X - Xn, f1, f2);
#pragma unroll
            for (int j = 0; j < 10; j++) a[j] = (a[j] * f1) * f2;
            X = Xn;
            const int Xp = __shfl_up_sync(FULL, X, 1);
            twoFactor(Xp - X, sD1, sD2);
            if (lane == 0) { sD1 = 0.f; sD2 = 0.f; }
        };

        // Pipelined flag check: pend covers rows t+6..t+11 of this group.
        int pend = (lane < 6) ? ldcg_s32(flg + 7 + lane) : 1;
        int t = 1;
        for (; t + 5 <= mid; t += 6) {
            while (!__all_sync(FULL, pend != 0))
                pend = (lane < 6) ? ldcg_s32(flg + t + 6 + lane) : 1;
            const int npend = (lane < 6) ? ldcg_s32(flg + t + 12 + lane) : 1;
            dostep(P[0]); pref(P[0], t + 6);
            dostep(P[1]); pref(P[1], t + 7);
            dostep(P[2]); pref(P[2], t + 8);
            dostep(P[3]); pref(P[3], t + 9);
            dostep(P[4]); pref(P[4], t + 10);
            dostep(P[5]); pref(P[5], t + 11);
            rescale();
            pend = npend;
        }
        if (t <= mid) { dostep(P[0]); ++t; }
        if (t <= mid) { dostep(P[1]); ++t; }
        if (t <= mid) { dostep(P[2]); ++t; }
        if (t <= mid) { dostep(P[3]); ++t; }
        if (t <= mid) { dostep(P[4]); ++t; }

#pragma unroll
        for (int j = 0; j < 10; j++) AFs[10 * lane + j] = a[j];
        XFs[lane] = X;
        if (lane == 0) LGs[0] = lgsum;

        // Wait for backward warp's results (volatile smem handshake).
        if (lane == 0) {
            while (*(volatile int*)&doneB == 0) { }
        }
        __syncwarp();
        __threadfence_block();

        // ===== Combine: log2 L = LSE_s [lg aF + XF + lg bB + XB] + lgsums ===
        float ys[9];
        float ymax = -1e30f;
#pragma unroll
        for (int k = 0; k < 9; k++) {
            const int s = lane + 32 * k;
            float y = -1e30f;
            if (s < kS) {
                const float af = AFs[s], bb = BBs[s];
                if (af > 0.f && bb > 0.f)
                    y = log2f(af) + log2f(bb) + (float)(XFs[s / 10] + XBs[s / 10]);
            }
            ys[k] = y;
            ymax = fmaxf(ymax, y);
        }
#pragma unroll
        for (int o = 16; o; o >>= 1) ymax = fmaxf(ymax, __shfl_xor_sync(FULL, ymax, o));
        float ssum = 0.f;
#pragma unroll
        for (int k = 0; k < 9; k++) ssum += exp2f(ys[k] - ymax);
#pragma unroll
        for (int o = 16; o; o >>= 1) ssum += __shfl_xor_sync(FULL, ssum, o);
        if (lane == 0) {
            const float rr = ymax + log2f(ssum) + LGs[0] + LGs[1];
            g_nll[b] = -rr * 0.69314718055994530942f;   // log2 -> ln
        }
    } else {
        // ===================== BACKWARD (beta), t = Tb-1..mid ===============
        float allowB[5];
#pragma unroll
        for (int k = 0; k < 5; k++) {
            const int li = 5 * lane + k + 1;
            bool al = false;
            if (li < kL) al = (lab[li] != lab[li - 1]);
            allowB[k] = al ? 1.0f : 0.0f;
        }

        const int sBl = 2 * len, sLl = sBl - 1;
        float bv[10];
#pragma unroll
        for (int j = 0; j < 10; j++) {
            const int s = 10 * lane + j;
            bv[j] = (s == sBl || s == sLl) ? 1.f : 0.f;
        }
        float lgsum = 0.f;
        int   X   = 0;
        float sB1 = (lane == 31) ? 0.f : 1.f;
        float sB2 = (lane == 31) ? 0.f : 1.f;

        // Wait distances 0..5 (rows Tb-1 .. Tb-6).
        {
            int ok;
            do {
                const int f = (lane < 6) ? ldcg_s32(flg + Tb - 1 - lane) : 1;
                ok = __all_sync(FULL, f != 0);
            } while (!ok);
        }

        float4 P[6][2];
#pragma unroll
        for (int q = 0; q < 6; q++) {
            const float* r = Eb + (size_t)(Tb - 1 - q) * kRow;
            P[q][0] = ldcg4(r + 4 * lane);
            P[q][1] = ldcg4(r + 128 + 4 * lane);
        }

        auto dostepB = [&](const float4* Pq) {
            const float bl = Pq[1].y;
            lgsum += Pq[1].z;
            float c[10];
            c[0] = bv[0] * bl;  c[1] = bv[1] * Pq[0].x;
            c[2] = bv[2] * bl;  c[3] = bv[3] * Pq[0].y;
            c[4] = bv[4] * bl;  c[5] = bv[5] * Pq[0].z;
            c[6] = bv[6] * bl;  c[7] = bv[7] * Pq[0].w;
            c[8] = bv[8] * bl;  c[9] = bv[9] * Pq[1].x;
            float h0 = __shfl_down_sync(FULL, c[0], 1);
            float h1 = __shfl_down_sync(FULL, c[1], 1);
            h0 = (h0 * sB1) * sB2;
            h1 = (h1 * sB1) * sB2;
            float nb[10];
            nb[0] = c[0] + c[1];
            nb[1] = fmaf(allowB[0], c[3], c[1] + c[2]);
            nb[2] = c[2] + c[3];
            nb[3] = fmaf(allowB[1], c[5], c[3] + c[4]);
            nb[4] = c[4] + c[5];
            nb[5] = fmaf(allowB[2], c[7], c[5] + c[6]);
            nb[6] = c[6] + c[7];
            nb[7] = fmaf(allowB[3], c[9], c[7] + c[8]);
            nb[8] = c[8] + c[9];
            nb[9] = fmaf(allowB[4], h1,   c[9] + h0);
#pragma unroll
            for (int j = 0; j < 10; j++) bv[j] = nb[j];
        };
        auto prefB = [&](float4* Pq, int dd) {
            const float* r = Eb + (size_t)(Tb - 1 - dd) * kRow;
            Pq[0] = ldcg4(r + 4 * lane);
            Pq[1] = ldcg4(r + 128 + 4 * lane);
        };
        auto rescaleB = [&]() {
            float mm = bv[0];
#pragma unroll
            for (int j = 1; j < 10; j++) mm = fmaxf(mm, bv[j]);
            const bool nz = (mm > 0.f);
            const int  e    = nz ? (((__float_as_int(mm) >> 23) & 0xff) - 127) : 0;
            const int  cand = nz ? (X + e) : NEGI;
            const int  c1 = __shfl_down_sync(FULL, cand, 1);
            const int  c2 = __shfl_down_sync(FULL, cand, 2);
            int Xn;
            if (lane == 31) {
                Xn = nz ? cand : X;
            } else {
                const int low  = max(c1 - 24, c2 - 48);
                const int ownc = nz ? cand : NEGI;
                Xn = max(ownc, low);
                if (Xn <= NEGI) Xn = X;
            }
            float f1, f2;
            twoFactor(X - Xn, f1, f2);
#pragma unroll
            for (int j = 0; j < 10; j++) bv[j] = (bv[j] * f1) * f2;
            X = Xn;
            const int Xp = __shfl_down_sync(FULL, X, 1);
            twoFactor(Xp - X, sB1, sB2);
            if (lane == 31) { sB1 = 0.f; sB2 = 0.f; }
        };

        // Pipelined flag check: pend covers distances d+6..d+11.
        int pend = (lane < 6) ? ldcg_s32(flg + Tb - 7 - lane) : 1;
        int d = 0;
        for (; d + 6 <= rem; d += 6) {
            while (!__all_sync(FULL, pend != 0))
                pend = (lane < 6) ? ldcg_s32(flg + Tb - 7 - d - lane) : 1;
            const int npend = (lane < 6) ? ldcg_s32(flg + Tb - 13 - d - lane) : 1;
            dostepB(P[0]); prefB(P[0], d + 6);
            dostepB(P[1]); prefB(P[1], d + 7);
            dostepB(P[2]); prefB(P[2], d + 8);
            dostepB(P[3]); prefB(P[3], d + 9);
            dostepB(P[4]); prefB(P[4], d + 10);
            dostepB(P[5]); prefB(P[5], d + 11);
            rescaleB();
            pend = npend;
        }
        if (d < rem) { dostepB(P[0]); ++d; }
        if (d < rem) { dostepB(P[1]); ++d; }
        if (d < rem) { dostepB(P[2]); ++d; }
        if (d < rem) { dostepB(P[3]); ++d; }
        if (d < rem) { dostepB(P[4]); ++d; }

#pragma unroll
        for (int j = 0; j < 10; j++) BBs[10 * lane + j] = bv[j];
        XBs[lane] = X;
        if (lane == 0) LGs[1] = lgsum;

        // Publish: results visible before the done flag.
        __syncwarp();
        __threadfence_block();
        if (lane == 0) *(volatile int*)&doneB = 1;
    }
}

// ---------------------------------------------------------------------------
// Kernel 3: mean over batch -> d_out[0]. Deterministic (no atomics).
// ---------------------------------------------------------------------------
__global__ void ctc_finish_kernel(float* __restrict__ out)
{
    float v = g_nll[threadIdx.x];
#pragma unroll
    for (int o = 16; o; o >>= 1) v += __shfl_xor_sync(0xffffffffu, v, o);
    if (threadIdx.x == 0) out[0] = v * (1.0f / kB);
}

extern "C" void kernel_launch(void* const* d_in, const int* in_sizes, int n_in,
                              void* d_out, int out_size)
{
    const int*   labels       = (const int*)d_in[0];
    const float* data         = (const float*)d_in[1];
    const int*   label_length = (const int*)d_in[2];
    const int*   data_length  = (const int*)d_in[3];
    float*       out          = (float*)d_out;

    ctc_zero_kernel<<<(kB * kTP + 255) / 256, 256>>>();
    ctc_fused_kernel<<<kGrid, 256>>>(data, labels, label_length, data_length);
    ctc_finish_kernel<<<1, 32>>>(out);
}